// round 7
// baseline (speedup 1.0000x reference)
#include <cuda_runtime.h>
#include <math.h>

#define Bc   8
#define Sc   8192
#define Vc   64
#define Dc   256
#define DVc  32
#define DAGG 224     // D - DV
#define NTOK (Bc*Sc) // 65536
#define NBV  (Bc*Vc) // 512
#define CAP  Sc      // worst-case tokens per (b,v) segment
#define ABC_BLKS 32
#define NBLK 128     // grid size: <= 148 SMs -> all co-resident, spin barriers safe

// ---------------- scratch (device globals; no allocation) ----------------
__device__ float  g_A[DAGG], g_Bv[DAGG], g_C[DAGG];
__device__ float  g_part[ABC_BLKS][3][DAGG];
__device__ int    g_abc_ctr = 0;                           // self-resetting
__device__ float  g_pa[3][Dc], g_pb[3][Dc], g_pc[3][Dc];   // 0=q,1=k,2=v
__device__ float  g_Pvar[3][Vc][Dc];                       // var_emb @ W[0:32,:]
__device__ int    g_cnt[NBV];
__device__ float2 g_tok[NBV * CAP];                        // (val,tt) per segment
__device__ float  g_ctx[Bc][Dc];
__device__ float  g_sf[Bc][Dc];
__device__ float  g_p2b[Bc];
__device__ int    g_ctr2[Bc];                              // zero-init, self-resetting
__device__ int    g_maskflags = 0;   // bit0: byte, bit1: float (OR idempotent across replays)

// ---------------- grid barrier (sense-reversing, replay-safe) ----------------
__device__ int               g_bar_cnt = 0;
__device__ volatile unsigned g_bar_gen = 0;

__device__ __forceinline__ void gridbar(unsigned& gen) {
    __syncthreads();
    if (threadIdx.x == 0) {
        __threadfence();
        unsigned g = gen;
        if (atomicAdd(&g_bar_cnt, 1) == NBLK - 1) {
            g_bar_cnt = 0;
            __threadfence();
            g_bar_gen = g + 1;
        } else {
            while (g_bar_gen == g) __nanosleep(64);
        }
    }
    __syncthreads();
    gen = gen + 1;
    __threadfence_block();
}

// ---------------- mega kernel ----------------
__global__ void __launch_bounds__(256) k_mega(
        const float* __restrict__ times, const int* __restrict__ fid,
        const float* __restrict__ values, const void* __restrict__ mask,
        const float* __restrict__ me_w, const float* __restrict__ me_b,
        const float* __restrict__ var_emb,
        const float* __restrict__ time_w, const float* __restrict__ time_b,
        const float* __restrict__ agg_w, const float* __restrict__ agg_b,
        const float* __restrict__ wq, const float* __restrict__ bq,
        const float* __restrict__ wk, const float* __restrict__ bk,
        const float* __restrict__ wv, const float* __restrict__ bvv,
        const float* __restrict__ wo, const float* __restrict__ bo,
        const float* __restrict__ cw1, const float* __restrict__ cb1,
        const float* __restrict__ cw2, const float* __restrict__ cb2,
        float* __restrict__ out) {
    const int blk = blockIdx.x;
    const int tid = threadIdx.x;

    __shared__ unsigned s_gen0;
    if (tid == 0) s_gen0 = g_bar_gen;
    __syncthreads();
    unsigned gen = s_gen0;

    // ================= P0: ABC partials | mask detect | zero =================
    if (blk < ABC_BLKS) {
        int j = tid;
        __shared__ bool isLast;
        if (j < DAGG) {
            float a = 0.f, b = 0.f, c = 0.f;
            int i0 = blk * 16;
            #pragma unroll
            for (int ii = 0; ii < 16; ii++) {
                int i = i0 + ii;
                if (i < 256) {
                    float w = agg_w[i * DAGG + j];
                    a += me_w[i] * w;  c += me_b[i] * w;
                } else {
                    int k = i - 256;
                    float w = agg_w[(256 + k) * DAGG + j];
                    b += time_w[k] * w;  c += time_b[k] * w;
                }
            }
            g_part[blk][0][j] = a;
            g_part[blk][1][j] = b;
            g_part[blk][2][j] = c;
        }
        __threadfence();
        __syncthreads();
        if (tid == 0)
            isLast = (atomicAdd(&g_abc_ctr, 1) == ABC_BLKS - 1);
        __syncthreads();
        if (isLast) {
            if (j < DAGG) {
                float a = 0.f, b = 0.f, c = 0.f;
                #pragma unroll
                for (int r = 0; r < ABC_BLKS; r++) {
                    a += __ldcg(&g_part[r][0][j]);
                    b += __ldcg(&g_part[r][1][j]);
                    c += __ldcg(&g_part[r][2][j]);
                }
                g_A[j] = a; g_Bv[j] = b; g_C[j] = c + agg_b[j];
            }
            if (tid == 0) g_abc_ctr = 0;
        }
    } else if (blk < ABC_BLKS + 8) {
        const unsigned int* w32 = (const unsigned int*)mask;
        int flags = 0;
        int base = (blk - ABC_BLKS) * 2048 + tid;
        #pragma unroll
        for (int t = 0; t < 8; t++) {
            unsigned int w = w32[base + t * 256];
            if (w == 0x3f800000u) flags |= 2;
            else if (w > 1u)      flags |= 1;
        }
        __shared__ int sfl;
        if (tid == 0) sfl = 0;
        __syncthreads();
        if (flags) atomicOr(&sfl, flags);
        __syncthreads();
        if (tid == 0 && sfl) atomicOr(&g_maskflags, sfl);
    } else if (blk < ABC_BLKS + 8 + 26) {
        int i = (blk - ABC_BLKS - 8) * 256 + tid;        // 0..6655
        if (i < NBV) g_cnt[i] = 0;
        else if (i < NBV + Bc * Dc)     ((float*)g_ctx)[i - NBV] = 0.f;
        else if (i < NBV + 2 * Bc * Dc) ((float*)g_sf)[i - NBV - Bc * Dc] = 0.f;
        else if (i < NBV + 2 * Bc * Dc + Bc) g_p2b[i - NBV - 2 * Bc * Dc] = 0.f;
    }
    gridbar(gen);

    // ================= P1: projection constants | token scan =================
    {
        int fl = g_maskflags;  // published before barrier
        for (int u = blk; u < 329; u += NBLK) {
            if (u < 201) {
                int p = u / 67, row = u % 67;
                const float* W  = (p == 0) ? wq : (p == 1 ? wk : wv);
                const float* bb = (p == 0) ? bq : (p == 1 ? bk : bvv);
                int j = tid;
                if (row < Vc) {
                    const float* ve = &var_emb[row * DVc];
                    float s = 0.f;
                    #pragma unroll
                    for (int i = 0; i < DVc; i++) s += ve[i] * W[i * Dc + j];
                    g_Pvar[p][row][j] = s;
                } else {
                    const float* src = (row == Vc) ? g_A : (row == Vc + 1 ? g_Bv : g_C);
                    float s = 0.f;
                    #pragma unroll 8
                    for (int i = 0; i < DAGG; i++)
                        s += __ldcg(&src[i]) * W[(DVc + i) * Dc + j];
                    if      (row == Vc)     g_pa[p][j] = s;
                    else if (row == Vc + 1) g_pb[p][j] = s;
                    else                    g_pc[p][j] = s + bb[j];
                }
            } else {
                // token scan: 2 tokens per thread
                int tp = (u - 201) * 256 + tid;          // pair index
                bool ok0, ok1;
                if (fl & 2) {
                    float2 m2 = ((const float2*)mask)[tp];
                    ok0 = m2.x != 0.f; ok1 = m2.y != 0.f;
                } else if (fl & 1) {
                    unsigned short us = ((const unsigned short*)mask)[tp];
                    ok0 = (us & 0xffu) != 0; ok1 = (us & 0xff00u) != 0;
                } else {
                    int2 m2 = ((const int2*)mask)[tp];
                    ok0 = m2.x != 0; ok1 = m2.y != 0;
                }
                if (ok0 | ok1) {
                    float2 vv = ((const float2*)values)[tp];
                    float2 tt = ((const float2*)times)[tp];
                    int2   ff = ((const int2*)fid)[tp];
                    int b = (tp * 2) >> 13;
                    if (ok0) {
                        int bv = b * Vc + ff.x;
                        int pos = atomicAdd(&g_cnt[bv], 1);
                        g_tok[bv * CAP + pos] = make_float2(vv.x, tt.x);
                    }
                    if (ok1) {
                        int bv = b * Vc + ff.y;
                        int pos = atomicAdd(&g_cnt[bv], 1);
                        g_tok[bv * CAP + pos] = make_float2(vv.y, tt.y);
                    }
                }
            }
        }
    }
    gridbar(gen);

    // ================= P2: segmented attention (4 segments/block) =================
    {
        int lane = tid & 31;
        for (int bv = blk; bv < NBV; bv += NBLK) {
            int b = bv >> 6, v = bv & (Vc - 1);
            int n = __ldcg(&g_cnt[bv]);

            float va = __ldcg(&g_pa[2][tid]), vb = __ldcg(&g_pb[2][tid]), vc = __ldcg(&g_pc[2][tid]);

            if (n == 0) {
                int t0 = b * Sc;
                float vx = __ldcg(&g_Pvar[2][fid[t0]][tid]) + values[t0] * va + times[t0] * vb + vc;
                atomicAdd(&g_ctx[b][tid], vx);
                continue;
            }

            const float2* tok = &g_tok[bv * CAP];

            float s_v = 0.f, s_t = 0.f;
            for (int i = lane; i < n; i += 32) {
                float2 vt = __ldcg(&tok[i]);
                s_v += vt.x; s_t += vt.y;
            }
            #pragma unroll
            for (int o = 16; o > 0; o >>= 1) {
                s_v += __shfl_xor_sync(0xffffffffu, s_v, o);
                s_t += __shfl_xor_sync(0xffffffffu, s_t, o);
            }
            float inv_n = 1.0f / (float)n;
            float mv = s_v * inv_n, mt = s_t * inv_n;

            float q  = __ldcg(&g_Pvar[0][v][tid]) + mv * __ldcg(&g_pa[0][tid])
                     + mt * __ldcg(&g_pb[0][tid]) + __ldcg(&g_pc[0][tid]);
            float kk = __ldcg(&g_Pvar[1][v][tid]) + __ldcg(&g_pc[1][tid]);

            const float scale = 0.17677669529663687f;  // 1/sqrt(32)
            float al = q * kk;
            float be = q * __ldcg(&g_pa[1][tid]);
            float ga = q * __ldcg(&g_pb[1][tid]);
            #pragma unroll
            for (int o = 16; o > 0; o >>= 1) {
                al += __shfl_xor_sync(0xffffffffu, al, o);
                be += __shfl_xor_sync(0xffffffffu, be, o);
                ga += __shfl_xor_sync(0xffffffffu, ga, o);
            }
            al *= scale; be *= scale; ga *= scale;

            float m = -1e30f, l = 0.f, sv = 0.f, st = 0.f;
            for (int i = lane; i < n; i += 32) {
                float2 vt = __ldcg(&tok[i]);
                float s  = al + be * vt.x + ga * vt.y;
                float nm = fmaxf(m, s);
                float c  = __expf(m - nm);
                float e  = __expf(s - nm);
                l  = l * c + e;
                sv = sv * c + e * vt.x;
                st = st * c + e * vt.y;
                m = nm;
            }
            #pragma unroll
            for (int o = 16; o > 0; o >>= 1) {
                float m2  = __shfl_xor_sync(0xffffffffu, m, o);
                float l2  = __shfl_xor_sync(0xffffffffu, l, o);
                float sv2 = __shfl_xor_sync(0xffffffffu, sv, o);
                float st2 = __shfl_xor_sync(0xffffffffu, st, o);
                float nm = fmaxf(m, m2);
                float c1 = __expf(m - nm), c2 = __expf(m2 - nm);
                l  = l * c1 + l2 * c2;
                sv = sv * c1 + sv2 * c2;
                st = st * c1 + st2 * c2;
                m = nm;
            }
            float wvv = sv / l, wtt = st / l;
            float ctx = __ldcg(&g_Pvar[2][v][tid]) + vc + wvv * va + wtt * vb;
            atomicAdd(&g_ctx[b][tid], ctx);
        }
    }
    gridbar(gen);

    // ================= P3: GEMV1 (f = ctx_mean @ wo + bo), 128 tiles =================
    __shared__ float sm[Dc];
    __shared__ float part[16][16];
    {
        int b = blk >> 4, cs = blk & 15;
        int c = tid & 15, r = tid >> 4;
        int col = cs * 16 + c;
        sm[tid] = __ldcg(&g_ctx[0][0] + b * Dc + tid) * (1.0f / Vc);
        __syncthreads();
        float acc = 0.f;
        #pragma unroll
        for (int ii = 0; ii < 16; ii++) {
            int i = r * 16 + ii;
            acc += sm[i] * wo[i * Dc + col];
        }
        part[r][c] = acc;
        __syncthreads();
        #pragma unroll
        for (int s = 8; s > 0; s >>= 1) {
            if (r < s) part[r][c] += part[r + s][c];
            __syncthreads();
        }
        if (r == 0) g_sf[b][col] = part[0][c] + bo[col];
    }
    gridbar(gen);

    // ================= P4: GEMV2 + relu + dot, per-b finalize =================
    {
        int b = blk >> 4, cs = blk & 15;
        int c = tid & 15, r = tid >> 4;
        int col = cs * 16 + c;
        sm[tid] = __ldcg(&g_sf[0][0] + b * Dc + tid);
        __syncthreads();
        float acc = 0.f;
        #pragma unroll
        for (int ii = 0; ii < 16; ii++) {
            int i = r * 16 + ii;
            acc += sm[i] * cw1[i * Dc + col];
        }
        part[r][c] = acc;
        __syncthreads();
        #pragma unroll
        for (int s = 8; s > 0; s >>= 1) {
            if (r < s) part[r][c] += part[r + s][c];
            __syncthreads();
        }
        if (r == 0) {
            float h = fmaxf(part[0][c] + cb1[col], 0.f);
            float s = h * cw2[col];
            #pragma unroll
            for (int o = 8; o > 0; o >>= 1)
                s += __shfl_xor_sync(0x0000ffffu, s, o);
            if (c == 0) atomicAdd(&g_p2b[b], s);
        }
        __threadfence();
        __syncthreads();
        if (tid == 0) {
            int done = atomicAdd(&g_ctr2[b], 1);
            if (done == 15) {
                out[b] = __ldcg(&g_p2b[b]) + cb2[0];
                g_ctr2[b] = 0;   // reset for next replay
            }
        }
    }
}

// ---------------- launch ----------------
extern "C" void kernel_launch(void* const* d_in, const int* in_sizes, int n_in,
                              void* d_out, int out_size) {
    const float* times   = (const float*)d_in[0];
    const int*   fid     = (const int*)  d_in[1];
    const float* values  = (const float*)d_in[2];
    const void*  mask    = (const void*) d_in[3];
    const float* me_w    = (const float*)d_in[4];
    const float* me_b    = (const float*)d_in[5];
    const float* var_emb = (const float*)d_in[6];
    const float* time_w  = (const float*)d_in[7];
    const float* time_b  = (const float*)d_in[8];
    const float* agg_w   = (const float*)d_in[9];
    const float* agg_b   = (const float*)d_in[10];
    const float* wq = (const float*)d_in[11]; const float* bq  = (const float*)d_in[12];
    const float* wk = (const float*)d_in[13]; const float* bk  = (const float*)d_in[14];
    const float* wv = (const float*)d_in[15]; const float* bvv = (const float*)d_in[16];
    const float* wo = (const float*)d_in[17]; const float* bo  = (const float*)d_in[18];
    const float* cw1 = (const float*)d_in[19]; const float* cb1 = (const float*)d_in[20];
    const float* cw2 = (const float*)d_in[21]; const float* cb2 = (const float*)d_in[22];
    float* out = (float*)d_out;

    k_mega<<<NBLK, 256>>>(times, fid, values, mask,
                          me_w, me_b, var_emb, time_w, time_b, agg_w, agg_b,
                          wq, bq, wk, bk, wv, bvv, wo, bo,
                          cw1, cb1, cw2, cb2, out);
}

// round 9
// speedup vs baseline: 1.4202x; 1.4202x over previous
#include <cuda_runtime.h>

#define Bc   8
#define Sc   8192
#define Vc   64
#define Dc   256
#define DVc  32
#define DAGG 224
#define NTOK (Bc*Sc)
#define NBV  (Bc*Vc)
#define CAP  Sc
#define ABC_BLKS  32
#define SCAN_BLKS 128
#define VEC_BLKS  9
#define K1_BLKS  (ABC_BLKS + SCAN_BLKS + VEC_BLKS)

// ---------------- scratch (device globals, zero-initialized; every mutated
// accumulator/counter self-resets after consumption -> graph-replay safe) ----
__device__ float  g_A[DAGG], g_Bv[DAGG], g_C[DAGG];
__device__ float  g_part[ABC_BLKS][3][DAGG];
__device__ int    g_abc_ctr;
__device__ volatile int g_abc_flag;
__device__ int    g_vec_ctr;
__device__ float  g_pa[3][Dc], g_pb[3][Dc], g_pc[3][Dc];   // 0=q,1=k,2=v
__device__ int    g_cnt[NBV];
__device__ float2 g_tok[NBV * CAP];
__device__ float  g_SV0[Dc];            // sum over v of V0[v][:]
__device__ float  g_corr[Bc][Dc];       // empty-segment vector corrections
__device__ float  g_sumwv[Bc][8], g_sumwt[Bc][8];  // per (b,head)
__device__ float  g_sf[Bc][Dc];
__device__ float  g_p2b[Bc];
__device__ int    g_ctr3[Bc], g_ctr3g, g_ctr4[Bc];
__device__ int    g_maskflags;          // sticky union (bit0 = byte layout)

// ============ K1: ABC partials | token scan (self-detect) | q/k/v vectors ===
__global__ void __launch_bounds__(256) k1(
        const float* __restrict__ me_w, const float* __restrict__ me_b,
        const float* __restrict__ time_w, const float* __restrict__ time_b,
        const float* __restrict__ agg_w, const float* __restrict__ agg_b,
        const void* __restrict__ mask,
        const int* __restrict__ fid, const float* __restrict__ values,
        const float* __restrict__ times,
        const float* __restrict__ wq, const float* __restrict__ bq,
        const float* __restrict__ wk, const float* __restrict__ bk,
        const float* __restrict__ wv, const float* __restrict__ bv) {
    const int blk = blockIdx.x, tid = threadIdx.x;

    if (blk < ABC_BLKS) {
        // ---- rank-2 collapse partials ----
        int j = tid;
        __shared__ bool isLast;
        if (j < DAGG) {
            float a = 0.f, b = 0.f, c = 0.f;
            int i0 = blk * 16;
            #pragma unroll
            for (int ii = 0; ii < 16; ii++) {
                int i = i0 + ii;
                if (i < 256) {
                    float w = agg_w[i * DAGG + j];
                    a += me_w[i] * w;  c += me_b[i] * w;
                } else {
                    int k = i - 256;
                    float w = agg_w[(256 + k) * DAGG + j];
                    b += time_w[k] * w;  c += time_b[k] * w;
                }
            }
            g_part[blk][0][j] = a; g_part[blk][1][j] = b; g_part[blk][2][j] = c;
        }
        __threadfence();
        __syncthreads();
        if (tid == 0) isLast = (atomicAdd(&g_abc_ctr, 1) == ABC_BLKS - 1);
        __syncthreads();
        if (isLast) {
            if (j < DAGG) {
                float a = 0.f, b = 0.f, c = 0.f;
                #pragma unroll
                for (int r = 0; r < ABC_BLKS; r++) {
                    a += __ldcg(&g_part[r][0][j]);
                    b += __ldcg(&g_part[r][1][j]);
                    c += __ldcg(&g_part[r][2][j]);
                }
                g_A[j] = a; g_Bv[j] = b; g_C[j] = c + agg_b[j];
            }
            __threadfence();
            __syncthreads();
            if (tid == 0) { g_abc_ctr = 0; g_abc_flag = 1; }
        }
    } else if (blk < ABC_BLKS + SCAN_BLKS) {
        // ---- token scan, 512 tokens/block, local mask-layout detect ----
        int sb = blk - ABC_BLKS;
        int t0 = sb * 512;
        __shared__ int sfl;
        if (tid == 0) sfl = g_maskflags;    // sticky union from prior runs
        __syncthreads();
        if (tid < 128) {
            unsigned w = ((const unsigned*)mask)[(t0 >> 2) + tid];  // 512B window, in-bounds for any layout
            if (w > 1u && w != 0x3f800000u) atomicOr(&sfl, 1);       // packed-byte signature
        }
        __syncthreads();
        int fl = sfl;
        if (tid == 0 && fl) atomicOr(&g_maskflags, fl);

        int tp = sb * 256 + tid;            // token-pair index
        bool ok0, ok1;
        if (fl & 1) {
            unsigned short us = ((const unsigned short*)mask)[tp];
            ok0 = (us & 0xffu) != 0; ok1 = (us >> 8) != 0;
        } else {                            // int32 / float32: identical nonzero test
            int2 m2 = ((const int2*)mask)[tp];
            ok0 = m2.x != 0; ok1 = m2.y != 0;
        }
        if (ok0 | ok1) {
            float2 vv = ((const float2*)values)[tp];
            float2 tt = ((const float2*)times)[tp];
            int2   ff = ((const int2*)fid)[tp];
            int b = (tp * 2) >> 13;
            if (ok0) {
                int bvx = b * Vc + ff.x;
                int pos = atomicAdd(&g_cnt[bvx], 1);
                g_tok[bvx * CAP + pos] = make_float2(vv.x, tt.x);
            }
            if (ok1) {
                int bvx = b * Vc + ff.y;
                int pos = atomicAdd(&g_cnt[bvx], 1);
                g_tok[bvx * CAP + pos] = make_float2(vv.y, tt.y);
            }
        }
    } else {
        // ---- q/k/v projection vectors (needs A/B/C -> spin on flag) ----
        int u = blk - ABC_BLKS - SCAN_BLKS;   // 0..8
        if (tid == 0) { while (g_abc_flag == 0) __nanosleep(64); }
        __syncthreads();
        __threadfence();
        int p = u / 3, r = u % 3;
        const float* W  = (p == 0) ? wq : (p == 1 ? wk : wv);
        const float* bb = (p == 0) ? bq : (p == 1 ? bk : bv);
        const float* src = (r == 0) ? g_A : (r == 1 ? g_Bv : g_C);
        int j = tid;
        float s = 0.f;
        #pragma unroll 8
        for (int i = 0; i < DAGG; i++)
            s += __ldcg(&src[i]) * W[(DVc + i) * Dc + j];
        if      (r == 0) g_pa[p][j] = s;
        else if (r == 1) g_pb[p][j] = s;
        else             g_pc[p][j] = s + bb[j];
        __threadfence();
        __syncthreads();
        if (tid == 0) {
            if (atomicAdd(&g_vec_ctr, 1) == VEC_BLKS - 1) {
                g_vec_ctr = 0; g_abc_flag = 0;   // reset for next replay
            }
        }
    }
}

// ============ K2: per-v head coefficients + scalar segmented softmax ========
__global__ void __launch_bounds__(256) k2(
        const int* __restrict__ fid, const float* __restrict__ values,
        const float* __restrict__ times, const float* __restrict__ var_emb,
        const float* __restrict__ wq, const float* __restrict__ wk,
        const float* __restrict__ wvv) {
    const int v = blockIdx.x, tid = threadIdx.x;
    const int h = tid >> 5, lane = tid & 31;
    __shared__ float ve[DVc];
    __shared__ float sc[8][9];

    if (tid < DVc) ve[tid] = var_emb[v * DVc + tid];
    __syncthreads();

    int j = tid;
    float qa = g_pa[0][j], qb = g_pb[0][j];
    float ka = g_pa[1][j], kb = g_pb[1][j];
    float p0 = g_pc[0][j], k0 = g_pc[1][j], v0 = g_pc[2][j];
    #pragma unroll
    for (int i = 0; i < DVc; i++) {
        float e = ve[i];
        p0 += e * wq[i * Dc + j];
        k0 += e * wk[i * Dc + j];
        v0 += e * wvv[i * Dc + j];
    }
    atomicAdd(&g_SV0[j], v0);

    const float scale = 0.17677669529663687f;   // 1/sqrt(32)
    float x[9] = { p0 * k0, qa * k0, qb * k0,
                   p0 * ka, qa * ka, qb * ka,
                   p0 * kb, qa * kb, qb * kb };
    #pragma unroll
    for (int t = 0; t < 9; t++) {
        float s = x[t];
        #pragma unroll
        for (int o = 16; o > 0; o >>= 1) s += __shfl_xor_sync(0xffffffffu, s, o);
        if (lane == 0) sc[h][t] = s * scale;
    }
    __syncthreads();

    // warp h handles batch b = h for this v
    int b = h;
    int bv = b * Vc + v;
    int n = g_cnt[bv];

    if (n == 0) {
        // reference unmasks s=0 -> ctx = v_proj[b,0,:]
        int t0g = b * Sc;
        int f0 = fid[t0g];
        float val0 = values[t0g], tt0 = times[t0g];
        const float* vef = &var_emb[f0 * DVc];
        for (int j2 = lane; j2 < Dc; j2 += 32) {
            float d = 0.f;
            #pragma unroll
            for (int i = 0; i < DVc; i++) d += (vef[i] - ve[i]) * wvv[i * Dc + j2];
            atomicAdd(&g_corr[b][j2], d);
        }
        if (lane < 8) {
            atomicAdd(&g_sumwv[b][lane], val0);
            atomicAdd(&g_sumwt[b][lane], tt0);
        }
        return;
    }

    const float2* tok = &g_tok[bv * CAP];
    float s_v = 0.f, s_t = 0.f;
    for (int i = lane; i < n; i += 32) {
        float2 t = tok[i];
        s_v += t.x; s_t += t.y;
    }
    #pragma unroll
    for (int o = 16; o > 0; o >>= 1) {
        s_v += __shfl_xor_sync(0xffffffffu, s_v, o);
        s_t += __shfl_xor_sync(0xffffffffu, s_t, o);
    }
    float inv_n = 1.0f / (float)n;
    float mv = s_v * inv_n, mt = s_t * inv_n;

    float al[8], be[8], ga[8];
    #pragma unroll
    for (int t = 0; t < 8; t++) {
        al[t] = sc[t][0] + mv * sc[t][1] + mt * sc[t][2];
        be[t] = sc[t][3] + mv * sc[t][4] + mt * sc[t][5];
        ga[t] = sc[t][6] + mv * sc[t][7] + mt * sc[t][8];
    }

    float m[8], l[8], sv[8], st[8];
    #pragma unroll
    for (int t = 0; t < 8; t++) { m[t] = -1e30f; l[t] = 0.f; sv[t] = 0.f; st[t] = 0.f; }

    for (int i = lane; i < n; i += 32) {
        float2 t2 = tok[i];
        #pragma unroll
        for (int t = 0; t < 8; t++) {
            float s  = al[t] + be[t] * t2.x + ga[t] * t2.y;
            float nm = fmaxf(m[t], s);
            float c  = __expf(m[t] - nm);
            float e  = __expf(s - nm);
            l[t]  = l[t] * c + e;
            sv[t] = sv[t] * c + e * t2.x;
            st[t] = st[t] * c + e * t2.y;
            m[t] = nm;
        }
    }
    #pragma unroll
    for (int t = 0; t < 8; t++) {
        #pragma unroll
        for (int o = 16; o > 0; o >>= 1) {
            float m2  = __shfl_xor_sync(0xffffffffu, m[t], o);
            float l2  = __shfl_xor_sync(0xffffffffu, l[t], o);
            float sv2 = __shfl_xor_sync(0xffffffffu, sv[t], o);
            float st2 = __shfl_xor_sync(0xffffffffu, st[t], o);
            float nm = fmaxf(m[t], m2);
            float c1 = __expf(m[t] - nm), c2 = __expf(m2 - nm);
            l[t]  = l[t] * c1 + l2 * c2;
            sv[t] = sv[t] * c1 + sv2 * c2;
            st[t] = st[t] * c1 + st2 * c2;
            m[t] = nm;
        }
    }
    if (lane == 0) {
        #pragma unroll
        for (int t = 0; t < 8; t++) {
            atomicAdd(&g_sumwv[b][t], sv[t] / l[t]);
            atomicAdd(&g_sumwt[b][t], st[t] / l[t]);
        }
        g_cnt[bv] = 0;    // reset for next replay
    }
}

// ============ K3: reconstruct ctx_mean + GEMV1 =============================
__global__ void __launch_bounds__(256) k3(const float* __restrict__ wo,
                                          const float* __restrict__ bo) {
    int b = blockIdx.x >> 4, sl = blockIdx.x & 15;
    int tid = threadIdx.x;
    int hh = tid >> 5;
    __shared__ float sm[Dc];
    __shared__ float part[16][16];

    float ctx = g_SV0[tid] + g_corr[b][tid]
              + g_sumwv[b][hh] * g_pa[2][tid]
              + g_sumwt[b][hh] * g_pb[2][tid];
    sm[tid] = ctx * (1.0f / Vc);
    __syncthreads();

    int r = tid >> 4, c = tid & 15;
    int col = sl * 16 + c;
    float acc = 0.f;
    #pragma unroll
    for (int ii = 0; ii < 16; ii++)
        acc += sm[r * 16 + ii] * wo[(r * 16 + ii) * Dc + col];
    part[r][c] = acc;
    __syncthreads();
    #pragma unroll
    for (int s = 8; s > 0; s >>= 1) {
        if (r < s) part[r][c] += part[r + s][c];
        __syncthreads();
    }
    if (tid < 16) g_sf[b][sl * 16 + tid] = part[0][tid] + bo[sl * 16 + tid];

    // cleanup (after all reads of this block are done)
    __threadfence();
    __syncthreads();
    __shared__ bool lastb, lastg;
    if (tid == 0) {
        lastb = (atomicAdd(&g_ctr3[b], 1) == 15);
        lastg = (atomicAdd(&g_ctr3g, 1) == 127);
    }
    __syncthreads();
    if (lastb) {
        g_corr[b][tid] = 0.f;
        if (tid < 8)  g_sumwv[b][tid] = 0.f;
        else if (tid < 16) g_sumwt[b][tid - 8] = 0.f;
        if (tid == 0) g_ctr3[b] = 0;
    }
    if (lastg) {
        g_SV0[tid] = 0.f;
        if (tid == 0) g_ctr3g = 0;
    }
}

// ============ K4: GEMV2 + relu + dot + out =================================
__global__ void __launch_bounds__(256) k4(const float* __restrict__ cw1,
                                          const float* __restrict__ cb1,
                                          const float* __restrict__ cw2,
                                          const float* __restrict__ cb2,
                                          float* __restrict__ out) {
    int b = blockIdx.x >> 4, sl = blockIdx.x & 15;
    int tid = threadIdx.x;
    __shared__ float sm[Dc];
    __shared__ float part[16][16];

    sm[tid] = g_sf[b][tid];
    __syncthreads();

    int r = tid >> 4, c = tid & 15;
    int col = sl * 16 + c;
    float acc = 0.f;
    #pragma unroll
    for (int ii = 0; ii < 16; ii++)
        acc += sm[r * 16 + ii] * cw1[(r * 16 + ii) * Dc + col];
    part[r][c] = acc;
    __syncthreads();
    #pragma unroll
    for (int s = 8; s > 0; s >>= 1) {
        if (r < s) part[r][c] += part[r + s][c];
        __syncthreads();
    }
    if (tid < 16) {
        int colj = sl * 16 + tid;
        float h = fmaxf(part[0][tid] + cb1[colj], 0.f);
        float s = h * cw2[colj];
        #pragma unroll
        for (int o = 8; o > 0; o >>= 1) s += __shfl_xor_sync(0x0000ffffu, s, o);
        if (tid == 0) atomicAdd(&g_p2b[b], s);
    }
    __threadfence();
    __syncthreads();
    if (tid == 0) {
        if (atomicAdd(&g_ctr4[b], 1) == 15) {
            out[b] = g_p2b[b] + cb2[0];
            g_p2b[b] = 0.f;
            g_ctr4[b] = 0;
        }
    }
}

// ---------------- launch ----------------
extern "C" void kernel_launch(void* const* d_in, const int* in_sizes, int n_in,
                              void* d_out, int out_size) {
    const float* times   = (const float*)d_in[0];
    const int*   fid     = (const int*)  d_in[1];
    const float* values  = (const float*)d_in[2];
    const void*  mask    = (const void*) d_in[3];
    const float* me_w    = (const float*)d_in[4];
    const float* me_b    = (const float*)d_in[5];
    const float* var_emb = (const float*)d_in[6];
    const float* time_w  = (const float*)d_in[7];
    const float* time_b  = (const float*)d_in[8];
    const float* agg_w   = (const float*)d_in[9];
    const float* agg_b   = (const float*)d_in[10];
    const float* wq = (const float*)d_in[11]; const float* bq  = (const float*)d_in[12];
    const float* wk = (const float*)d_in[13]; const float* bk  = (const float*)d_in[14];
    const float* wv = (const float*)d_in[15]; const float* bvv = (const float*)d_in[16];
    const float* wo = (const float*)d_in[17]; const float* bo  = (const float*)d_in[18];
    const float* cw1 = (const float*)d_in[19]; const float* cb1 = (const float*)d_in[20];
    const float* cw2 = (const float*)d_in[21]; const float* cb2 = (const float*)d_in[22];
    float* out = (float*)d_out;

    k1<<<K1_BLKS, 256>>>(me_w, me_b, time_w, time_b, agg_w, agg_b, mask,
                         fid, values, times, wq, bq, wk, bk, wv, bvv);
    k2<<<Vc, 256>>>(fid, values, times, var_emb, wq, wk, wv);
    k3<<<128, 256>>>(wo, bo);
    k4<<<128, 256>>>(cw1, cb1, cw2, cb2, out);
}

// round 10
// speedup vs baseline: 1.5112x; 1.0640x over previous
#include <cuda_runtime.h>

#define Bc   8
#define Sc   8192
#define Vc   64
#define Dc   256
#define DVc  32
#define DAGG 224
#define CAP  Sc

#define SCAN_N 128
#define ABC_N  32
#define VEC_N  9
#define SCAN0  0
#define ABC0   (SCAN0 + SCAN_N)   // 128
#define VEC0   (ABC0 + ABC_N)     // 160
#define SV0B   (VEC0 + VEC_N)     // 169
#define UB0    (SV0B + 1)         // 170
#define SOFT0  (UB0 + 8)          // 178
#define FIN0   (SOFT0 + Vc)       // 242
#define NBLKS  (FIN0 + Bc)        // 250

// ---- device globals (zero-init; all mutated state self-resets) ----
__device__ float  g_A[DAGG], g_Bv[DAGG], g_C[DAGG];
__device__ float  g_part[ABC_N][3][DAGG];
__device__ int    g_abc_ctr;
__device__ int    g_vec_ctr;
__device__ int    g_fin_ctr;
__device__ volatile int g_abc_flag, g_vec_flag, g_sv0_flag;
__device__ volatile int g_scan_ctr, g_soft_ctr, g_u_ctr;
__device__ volatile int g_corrflag;
__device__ float  g_pa[3][Dc], g_pb[3][Dc], g_pc[3][Dc];   // 0=q,1=k,2=v
__device__ float  g_SV0[Dc];
__device__ int    g_cnt[Bc * Vc];
__device__ float2 g_tok[Bc * Vc * CAP];
__device__ float  g_corr[Bc][Dc];
__device__ float  g_sumwv[Bc][8], g_sumwt[Bc][8];
__device__ float  g_Ua[8][Dc], g_Ub[8][Dc], g_U0[Dc];
__device__ int    g_maskflags;          // sticky across replays (OR idempotent)

__global__ void __launch_bounds__(256) k_all(
        const float* __restrict__ times, const int* __restrict__ fid,
        const float* __restrict__ values, const void* __restrict__ mask,
        const float* __restrict__ me_w, const float* __restrict__ me_b,
        const float* __restrict__ var_emb,
        const float* __restrict__ time_w, const float* __restrict__ time_b,
        const float* __restrict__ agg_w, const float* __restrict__ agg_b,
        const float* __restrict__ wq, const float* __restrict__ bq,
        const float* __restrict__ wk, const float* __restrict__ bk,
        const float* __restrict__ wv, const float* __restrict__ bv,
        const float* __restrict__ wo, const float* __restrict__ bo,
        const float* __restrict__ cw1, const float* __restrict__ cb1,
        const float* __restrict__ cw2, const float* __restrict__ cb2,
        float* __restrict__ out) {
    const int blk = blockIdx.x, tid = threadIdx.x;

    if (blk < ABC0) {
        // ============ SCAN: 512 tokens/block, self-detect mask layout ============
        int sb = blk;
        __shared__ int sfl;
        if (tid == 0) sfl = g_maskflags;
        __syncthreads();
        if (tid < 128) {
            unsigned w = ((const unsigned*)mask)[sb * 128 + tid];  // in-bounds for any layout
            if (w > 1u && w != 0x3f800000u) atomicOr(&sfl, 1);      // packed-byte signature
        }
        __syncthreads();
        int fl = sfl;
        if (tid == 0 && fl) atomicOr(&g_maskflags, fl);

        int tp = sb * 256 + tid;
        bool ok0, ok1;
        if (fl & 1) {
            unsigned short us = ((const unsigned short*)mask)[tp];
            ok0 = (us & 0xffu) != 0; ok1 = (us >> 8) != 0;
        } else {
            int2 m2 = ((const int2*)mask)[tp];
            ok0 = m2.x != 0; ok1 = m2.y != 0;
        }
        if (ok0 | ok1) {
            float2 vvld = ((const float2*)values)[tp];
            float2 ttld = ((const float2*)times)[tp];
            int2   ffld = ((const int2*)fid)[tp];
            int b = (tp * 2) >> 13;
            if (ok0) {
                int bvx = b * Vc + ffld.x;
                int pos = atomicAdd(&g_cnt[bvx], 1);
                g_tok[bvx * CAP + pos] = make_float2(vvld.x, ttld.x);
            }
            if (ok1) {
                int bvx = b * Vc + ffld.y;
                int pos = atomicAdd(&g_cnt[bvx], 1);
                g_tok[bvx * CAP + pos] = make_float2(vvld.y, ttld.y);
            }
        }
        __threadfence();
        __syncthreads();
        if (tid == 0) atomicAdd((int*)&g_scan_ctr, 1);

    } else if (blk < VEC0) {
        // ============ ABC: rank-2 collapse partials + last-block reduce ============
        int ab = blk - ABC0;
        int j = tid;
        __shared__ bool isLast;
        if (j < DAGG) {
            float a = 0.f, b = 0.f, c = 0.f;
            int i0 = ab * 16;
            #pragma unroll
            for (int ii = 0; ii < 16; ii++) {
                int i = i0 + ii;
                if (i < 256) {
                    float w = agg_w[i * DAGG + j];
                    a += me_w[i] * w;  c += me_b[i] * w;
                } else {
                    int k = i - 256;
                    float w = agg_w[(256 + k) * DAGG + j];
                    b += time_w[k] * w;  c += time_b[k] * w;
                }
            }
            g_part[ab][0][j] = a; g_part[ab][1][j] = b; g_part[ab][2][j] = c;
        }
        __threadfence();
        __syncthreads();
        if (tid == 0) isLast = (atomicAdd(&g_abc_ctr, 1) == ABC_N - 1);
        __syncthreads();
        if (isLast) {
            if (j < DAGG) {
                float a = 0.f, b = 0.f, c = 0.f;
                #pragma unroll
                for (int r = 0; r < ABC_N; r++) {
                    a += __ldcg(&g_part[r][0][j]);
                    b += __ldcg(&g_part[r][1][j]);
                    c += __ldcg(&g_part[r][2][j]);
                }
                g_A[j] = a; g_Bv[j] = b; g_C[j] = c + agg_b[j];
            }
            __threadfence();
            __syncthreads();
            if (tid == 0) { g_abc_ctr = 0; g_abc_flag = 1; }
        }

    } else if (blk < SV0B) {
        // ============ VEC: pa/pb/pc = {A,B,C} @ W[32:,:] (+bias) ============
        int u = blk - VEC0;
        if (tid == 0) { while (!g_abc_flag) __nanosleep(128); }
        __syncthreads();
        __threadfence();
        int p = u / 3, r = u % 3;
        const float* W   = (p == 0) ? wq : (p == 1 ? wk : wv);
        const float* bbp = (p == 0) ? bq : (p == 1 ? bk : bv);
        const float* src = (r == 0) ? g_A : (r == 1 ? g_Bv : g_C);
        int j = tid;
        float s = 0.f;
        #pragma unroll 16
        for (int i = 0; i < DAGG; i++)
            s += __ldcg(&src[i]) * W[(DVc + i) * Dc + j];
        if      (r == 0) g_pa[p][j] = s;
        else if (r == 1) g_pb[p][j] = s;
        else             g_pc[p][j] = s + bbp[j];
        __threadfence();
        __syncthreads();
        if (tid == 0 && atomicAdd(&g_vec_ctr, 1) == VEC_N - 1) g_vec_flag = 1;

    } else if (blk < UB0) {
        // ============ SV0 = 64*pc2 + (col-sum var_emb) @ wv ============
        if (tid == 0) { while (!g_vec_flag) __nanosleep(128); }
        __syncthreads();
        __threadfence();
        __shared__ float sve[DVc];
        __shared__ float sp[8][DVc];
        int i = tid & 31, gz = tid >> 5;
        float p = 0.f;
        #pragma unroll
        for (int r = 0; r < 8; r++) p += var_emb[(gz * 8 + r) * DVc + i];
        sp[gz][i] = p;
        __syncthreads();
        if (gz == 0) {
            float s = 0.f;
            #pragma unroll
            for (int r = 0; r < 8; r++) s += sp[r][i];
            sve[i] = s;
        }
        __syncthreads();
        float s = 64.f * __ldcg(&g_pc[2][tid]);
        #pragma unroll
        for (int k = 0; k < DVc; k++) s += sve[k] * wv[k * Dc + tid];
        g_SV0[tid] = s;
        __threadfence();
        __syncthreads();
        if (tid == 0) g_sv0_flag = 1;

    } else if (blk < SOFT0) {
        // ============ U-vectors: U0, Ua[h], Ub[h] (32-col slice per block) ============
        int sl = blk - UB0;
        if (tid == 0) { while (!g_sv0_flag) __nanosleep(128); }
        __syncthreads();
        __threadfence();
        int w = tid >> 5, lane = tid & 31;
        int col = sl * 32 + lane;
        float aa = 0.f, bb2 = 0.f, cc = 0.f;
        #pragma unroll
        for (int k = 0; k < 32; k++) {
            int d = w * 32 + k;
            float wv_ = wo[d * Dc + col];
            aa  += __ldcg(&g_pa[2][d]) * wv_;
            bb2 += __ldcg(&g_pb[2][d]) * wv_;
            cc  += __ldcg(&g_SV0[d])   * wv_;
        }
        g_Ua[w][col] = aa * (1.f / 64.f);
        g_Ub[w][col] = bb2 * (1.f / 64.f);
        __shared__ float up[8][32];
        up[w][lane] = cc;
        __syncthreads();
        if (w == 0) {
            float s = 0.f;
            #pragma unroll
            for (int r = 0; r < 8; r++) s += up[r][lane];
            g_U0[col] = s * (1.f / 64.f) + bo[col];
        }
        __threadfence();
        __syncthreads();
        if (tid == 0) atomicAdd((int*)&g_u_ctr, 1);

    } else if (blk < FIN0) {
        // ============ SOFT: per-v head coefficients + scalar segmented softmax ====
        int v = blk - SOFT0;
        if (tid == 0) { while (!(g_vec_flag && g_scan_ctr >= SCAN_N)) __nanosleep(128); }
        __syncthreads();
        __threadfence();
        int h = tid >> 5, lane = tid & 31;
        __shared__ float ve[DVc];
        __shared__ float sc[8][9];
        if (tid < DVc) ve[tid] = var_emb[v * DVc + tid];
        __syncthreads();

        int j = tid;
        float qa = __ldcg(&g_pa[0][j]), qb = __ldcg(&g_pb[0][j]);
        float ka = __ldcg(&g_pa[1][j]), kb = __ldcg(&g_pb[1][j]);
        float p0 = __ldcg(&g_pc[0][j]), k0 = __ldcg(&g_pc[1][j]);
        #pragma unroll
        for (int i = 0; i < DVc; i++) {
            float e = ve[i];
            p0 += e * wq[i * Dc + j];
            k0 += e * wk[i * Dc + j];
        }
        const float scale = 0.17677669529663687f;   // 1/sqrt(32)
        float x[9] = { p0 * k0, qa * k0, qb * k0,
                       p0 * ka, qa * ka, qb * ka,
                       p0 * kb, qa * kb, qb * kb };
        #pragma unroll
        for (int t = 0; t < 9; t++) {
            float s = x[t];
            #pragma unroll
            for (int o = 16; o > 0; o >>= 1) s += __shfl_xor_sync(0xffffffffu, s, o);
            if (lane == 0) sc[h][t] = s * scale;
        }
        __syncthreads();

        // warp h handles batch b = h
        int b = h;
        int bvx = b * Vc + v;
        int n = __ldcg(&g_cnt[bvx]);

        if (n == 0) {
            // reference unmasks s=0 -> ctx = v_proj[b,0,:]
            int t0g = b * Sc;
            int f0 = fid[t0g];
            float val0 = values[t0g], tt0 = times[t0g];
            const float* vef = &var_emb[f0 * DVc];
            for (int j2 = lane; j2 < Dc; j2 += 32) {
                float d = 0.f;
                #pragma unroll
                for (int i = 0; i < DVc; i++) d += (vef[i] - ve[i]) * wv[i * Dc + j2];
                atomicAdd(&g_corr[b][j2], d);
            }
            if (lane == 0) g_corrflag = 1;
            if (lane < 8) {
                atomicAdd(&g_sumwv[b][lane], val0);
                atomicAdd(&g_sumwt[b][lane], tt0);
            }
        } else {
            const float2* tok = &g_tok[bvx * CAP];
            float s_v = 0.f, s_t = 0.f;
            for (int i = lane; i < n; i += 32) {
                float2 t = __ldcg(&tok[i]);
                s_v += t.x; s_t += t.y;
            }
            #pragma unroll
            for (int o = 16; o > 0; o >>= 1) {
                s_v += __shfl_xor_sync(0xffffffffu, s_v, o);
                s_t += __shfl_xor_sync(0xffffffffu, s_t, o);
            }
            float inv_n = 1.0f / (float)n;
            float mvv = s_v * inv_n, mtt = s_t * inv_n;

            float al[8], be[8], ga[8];
            #pragma unroll
            for (int t = 0; t < 8; t++) {
                al[t] = sc[t][0] + mvv * sc[t][1] + mtt * sc[t][2];
                be[t] = sc[t][3] + mvv * sc[t][4] + mtt * sc[t][5];
                ga[t] = sc[t][6] + mvv * sc[t][7] + mtt * sc[t][8];
            }
            float m[8], l[8], sv[8], st[8];
            #pragma unroll
            for (int t = 0; t < 8; t++) { m[t] = -1e30f; l[t] = 0.f; sv[t] = 0.f; st[t] = 0.f; }
            for (int i = lane; i < n; i += 32) {
                float2 t2 = __ldcg(&tok[i]);
                #pragma unroll
                for (int t = 0; t < 8; t++) {
                    float s  = al[t] + be[t] * t2.x + ga[t] * t2.y;
                    float nm = fmaxf(m[t], s);
                    float c  = __expf(m[t] - nm);
                    float e  = __expf(s - nm);
                    l[t]  = l[t] * c + e;
                    sv[t] = sv[t] * c + e * t2.x;
                    st[t] = st[t] * c + e * t2.y;
                    m[t] = nm;
                }
            }
            #pragma unroll
            for (int t = 0; t < 8; t++) {
                #pragma unroll
                for (int o = 16; o > 0; o >>= 1) {
                    float m2  = __shfl_xor_sync(0xffffffffu, m[t], o);
                    float l2  = __shfl_xor_sync(0xffffffffu, l[t], o);
                    float sv2 = __shfl_xor_sync(0xffffffffu, sv[t], o);
                    float st2 = __shfl_xor_sync(0xffffffffu, st[t], o);
                    float nm = fmaxf(m[t], m2);
                    float c1 = __expf(m[t] - nm), c2 = __expf(m2 - nm);
                    l[t]  = l[t] * c1 + l2 * c2;
                    sv[t] = sv[t] * c1 + sv2 * c2;
                    st[t] = st[t] * c1 + st2 * c2;
                    m[t] = nm;
                }
            }
            if (lane == 0) {
                #pragma unroll
                for (int t = 0; t < 8; t++) {
                    atomicAdd(&g_sumwv[b][t], sv[t] / l[t]);
                    atomicAdd(&g_sumwt[b][t], st[t] / l[t]);
                }
                g_cnt[bvx] = 0;    // reset for next replay
            }
        }
        __threadfence();
        __syncthreads();
        if (tid == 0) atomicAdd((int*)&g_soft_ctr, 1);

    } else {
        // ============ FIN: sf(b) = U0 + rank-16 combo (+corr), GEMV2, out ============
        int b = blk - FIN0;
        if (tid == 0) { while (!(g_soft_ctr >= Vc && g_u_ctr >= 8)) __nanosleep(128); }
        __syncthreads();
        __threadfence();
        int cfl = g_corrflag;
        float swv[8], swt[8];
        #pragma unroll
        for (int t = 0; t < 8; t++) {
            swv[t] = __ldcg(&g_sumwv[b][t]);
            swt[t] = __ldcg(&g_sumwt[b][t]);
        }
        int j = tid;
        float sf = __ldcg(&g_U0[j]);
        #pragma unroll
        for (int t = 0; t < 8; t++)
            sf += swv[t] * __ldcg(&g_Ua[t][j]) + swt[t] * __ldcg(&g_Ub[t][j]);
        if (cfl) {   // cold path: empty segments existed
            float cd = 0.f;
            for (int d = 0; d < Dc; d++) cd += __ldcg(&g_corr[b][d]) * wo[d * Dc + j];
            sf += cd * (1.f / 64.f);
        }
        __shared__ float ssf[Dc];
        __shared__ float red[Dc];
        ssf[j] = sf;
        __syncthreads();
        float acc = 0.f;
        #pragma unroll 32
        for (int i = 0; i < Dc; i++) acc += ssf[i] * cw1[i * Dc + j];
        float hh = fmaxf(acc + cb1[j], 0.f);
        red[j] = hh * cw2[j];
        __syncthreads();
        #pragma unroll
        for (int s = 128; s > 0; s >>= 1) {
            if (j < s) red[j] += red[j + s];
            __syncthreads();
        }
        if (j == 0) out[b] = red[0] + cb2[0];
        // resets
        if (tid < 8)       g_sumwv[b][tid] = 0.f;
        else if (tid < 16) g_sumwt[b][tid - 8] = 0.f;
        if (cfl) g_corr[b][tid] = 0.f;
        __threadfence();
        __syncthreads();
        if (tid == 0 && atomicAdd(&g_fin_ctr, 1) == Bc - 1) {
            g_scan_ctr = 0; g_soft_ctr = 0; g_u_ctr = 0; g_vec_ctr = 0;
            g_abc_flag = 0; g_vec_flag = 0; g_sv0_flag = 0; g_corrflag = 0;
            g_fin_ctr = 0;
        }
    }
}

// ---------------- launch ----------------
extern "C" void kernel_launch(void* const* d_in, const int* in_sizes, int n_in,
                              void* d_out, int out_size) {
    const float* times   = (const float*)d_in[0];
    const int*   fid     = (const int*)  d_in[1];
    const float* values  = (const float*)d_in[2];
    const void*  mask    = (const void*) d_in[3];
    const float* me_w    = (const float*)d_in[4];
    const float* me_b    = (const float*)d_in[5];
    const float* var_emb = (const float*)d_in[6];
    const float* time_w  = (const float*)d_in[7];
    const float* time_b  = (const float*)d_in[8];
    const float* agg_w   = (const float*)d_in[9];
    const float* agg_b   = (const float*)d_in[10];
    const float* wq = (const float*)d_in[11]; const float* bq  = (const float*)d_in[12];
    const float* wk = (const float*)d_in[13]; const float* bk  = (const float*)d_in[14];
    const float* wv = (const float*)d_in[15]; const float* bvv = (const float*)d_in[16];
    const float* wo = (const float*)d_in[17]; const float* bo  = (const float*)d_in[18];
    const float* cw1 = (const float*)d_in[19]; const float* cb1 = (const float*)d_in[20];
    const float* cw2 = (const float*)d_in[21]; const float* cb2 = (const float*)d_in[22];
    float* out = (float*)d_out;

    k_all<<<NBLKS, 256>>>(times, fid, values, mask,
                          me_w, me_b, var_emb, time_w, time_b, agg_w, agg_b,
                          wq, bq, wk, bk, wv, bvv, wo, bo,
                          cw1, cb1, cw2, cb2, out);
}